// round 2
// baseline (speedup 1.0000x reference)
#include <cuda_runtime.h>

// Problem constants: b=8, t=1024, e=256, h=8, e*h=2048, b*t=8192
#define BATCH 8
#define TSEQ  1024
#define EDIM  256
#define HEADS 8
#define EH    2048
#define ROWS  8192   // BATCH*TSEQ

// Scratch (static device globals -- allocation-free per harness rules)
__device__ __align__(16) float g_q[16777216];   // 8192 x 2048
__device__ __align__(16) float g_k[16777216];
__device__ __align__(16) float g_v[16777216];
__device__ __align__(16) float g_s[67108864];   // 64 x 1024 x 1024 (per b,h score/attn)
__device__ __align__(16) float g_o[16777216];   // 8192 x 2048 (attn @ v, (b,t,h*e))

// ---------------------------------------------------------------------------
// Common 64x64 tile GEMM core. 256 threads, 4x4 micro-tile, BK=16.
// A is row-major [64 rows x K], lda given, pre-offset to the tile's row 0.
// If TRANS_B: B is row-major [64 rows(of N) x K] (NT, dot of rows).
// Else:       B is row-major [K x 64 cols]       (NN).
// K must be a multiple of 16.
// ---------------------------------------------------------------------------
template<bool TRANS_B>
__device__ __forceinline__ void gemm_tile64(const float* __restrict__ A, int lda,
                                            const float* __restrict__ Bm, int ldb,
                                            int K, float acc[4][4])
{
    __shared__ __align__(16) float As[16][64];
    __shared__ __align__(16) float Bs[16][64];
    const int tid = threadIdx.x;
    const int tx = tid & 15;
    const int ty = tid >> 4;

    for (int k0 = 0; k0 < K; k0 += 16) {
        #pragma unroll
        for (int u = 0; u < 4; ++u) {
            int id = tid + u * 256;      // 0..1023
            int r = id >> 4, c = id & 15;
            As[c][r] = A[r * lda + k0 + c];
        }
        #pragma unroll
        for (int u = 0; u < 4; ++u) {
            int id = tid + u * 256;
            if (TRANS_B) {
                int r = id >> 4, c = id & 15;
                Bs[c][r] = Bm[r * ldb + k0 + c];
            } else {
                int r = id >> 6, c = id & 63;
                Bs[r][c] = Bm[(k0 + r) * ldb + c];
            }
        }
        __syncthreads();
        #pragma unroll
        for (int kk = 0; kk < 16; ++kk) {
            float4 a4 = *(const float4*)&As[kk][ty * 4];
            float4 b4 = *(const float4*)&Bs[kk][tx * 4];
            float av[4] = {a4.x, a4.y, a4.z, a4.w};
            float bv[4] = {b4.x, b4.y, b4.z, b4.w};
            #pragma unroll
            for (int i = 0; i < 4; ++i)
                #pragma unroll
                for (int j = 0; j < 4; ++j)
                    acc[i][j] = fmaf(av[i], bv[j], acc[i][j]);
        }
        __syncthreads();
    }
}

// ---------------------------------------------------------------------------
// 1) QKV projections: {Q,K,V}[8192 x 2048] = x[8192 x 256] @ W + bias
//    grid = (2048/64, 8192/64, 3)
// ---------------------------------------------------------------------------
__global__ __launch_bounds__(256)
void qkv_kernel(const float* __restrict__ x,
                const float* __restrict__ Wq, const float* __restrict__ bq,
                const float* __restrict__ Wk, const float* __restrict__ bk,
                const float* __restrict__ Wv, const float* __restrict__ bv)
{
    const int col0 = blockIdx.x * 64;
    const int row0 = blockIdx.y * 64;
    const int z = blockIdx.z;
    const float* W    = (z == 0) ? Wq : (z == 1) ? Wk : Wv;
    const float* bias = (z == 0) ? bq : (z == 1) ? bk : bv;
    float* outp       = (z == 0) ? g_q : (z == 1) ? g_k : g_v;

    float acc[4][4] = {};
    gemm_tile64<false>(x + (size_t)row0 * EDIM, EDIM, W + col0, EH, EDIM, acc);

    const int tx = threadIdx.x & 15, ty = threadIdx.x >> 4;
    #pragma unroll
    for (int i = 0; i < 4; ++i) {
        int m = row0 + ty * 4 + i;
        #pragma unroll
        for (int j = 0; j < 4; ++j) {
            int n = col0 + tx * 4 + j;
            outp[(size_t)m * EH + n] = acc[i][j] + bias[n];
        }
    }
}

// ---------------------------------------------------------------------------
// 2) Scores: S[bh][i][j] = (1/16) * dot(Q[b,i,h,:], K[b,j,h,:])  for j < i only.
//    grid = (16 jt, 16 it, 64 bh); tiles with jt > it are skipped.
// ---------------------------------------------------------------------------
__global__ __launch_bounds__(256)
void scores_kernel()
{
    const int jt = blockIdx.x, it = blockIdx.y, bh = blockIdx.z;
    if (jt > it) return;
    const int b = bh >> 3, h = bh & 7;

    const float* A = g_q + (size_t)b * TSEQ * EH + (size_t)(it * 64) * EH + h * EDIM;
    const float* Bm = g_k + (size_t)b * TSEQ * EH + (size_t)(jt * 64) * EH + h * EDIM;
    float* C = g_s + ((size_t)bh << 20);

    float acc[4][4] = {};
    gemm_tile64<true>(A, EH, Bm, EH, EDIM, acc);

    const int tx = threadIdx.x & 15, ty = threadIdx.x >> 4;
    #pragma unroll
    for (int i = 0; i < 4; ++i) {
        int gi = it * 64 + ty * 4 + i;
        #pragma unroll
        for (int j = 0; j < 4; ++j) {
            int gj = jt * 64 + tx * 4 + j;
            if (gj < gi)
                C[(size_t)gi * TSEQ + gj] = acc[i][j] * 0.0625f;
        }
    }
}

// ---------------------------------------------------------------------------
// 3) Softmax per row, in place in g_s. Valid entries are j < i; the rest of
//    the row is zero-filled (so the PV GEMM can run dense). Row i==0 -> zeros.
//    grid = 64*1024 blocks of 256 threads. Warp-shuffle reductions.
// ---------------------------------------------------------------------------
__global__ __launch_bounds__(256)
void softmax_kernel()
{
    const int row = blockIdx.x;          // bh*1024 + i
    const int i = row & (TSEQ - 1);
    float* p = g_s + (size_t)row * TSEQ;
    const int tid = threadIdx.x;

    if (i == 0) {
        for (int j = tid; j < TSEQ; j += 256) p[j] = 0.f;
        return;
    }

    __shared__ float red[8];
    const int lane = tid & 31, wid = tid >> 5;

    // --- max ---
    float m = -3.0e38f;
    for (int j = tid; j < i; j += 256) m = fmaxf(m, p[j]);
    #pragma unroll
    for (int s = 16; s > 0; s >>= 1) m = fmaxf(m, __shfl_xor_sync(0xffffffffu, m, s));
    if (lane == 0) red[wid] = m;
    __syncthreads();
    m = red[lane & 7];
    #pragma unroll
    for (int s = 4; s > 0; s >>= 1) m = fmaxf(m, __shfl_xor_sync(0xffffffffu, m, s));
    // m now uniform across each warp (all warps identical result)

    // --- sum ---
    float sum = 0.f;
    for (int j = tid; j < i; j += 256) sum += __expf(p[j] - m);
    #pragma unroll
    for (int s = 16; s > 0; s >>= 1) sum += __shfl_xor_sync(0xffffffffu, sum, s);
    __syncthreads();                     // reuse red[] safely
    if (lane == 0) red[wid] = sum;
    __syncthreads();
    sum = red[lane & 7];
    #pragma unroll
    for (int s = 4; s > 0; s >>= 1) sum += __shfl_xor_sync(0xffffffffu, sum, s);
    const float inv = 1.0f / sum;

    for (int j = tid; j < TSEQ; j += 256)
        p[j] = (j < i) ? __expf(p[j] - m) * inv : 0.f;
}

// ---------------------------------------------------------------------------
// 4) O[b,i,h,:] += sum_j P[bh][i][j] * V[b,j,h,:].
//    grid = (4 e'-tiles, 16 it, 64 bh). K clipped to (it+1)*64 (P is zero above).
// ---------------------------------------------------------------------------
__global__ __launch_bounds__(256)
void attnv_kernel()
{
    const int nt = blockIdx.x, it = blockIdx.y, bh = blockIdx.z;
    const int b = bh >> 3, h = bh & 7;

    const float* A = g_s + ((size_t)bh << 20) + (size_t)(it * 64) * TSEQ;
    const float* Bm = g_v + (size_t)b * TSEQ * EH + h * EDIM + nt * 64;
    float* C = g_o + (size_t)b * TSEQ * EH + h * EDIM + nt * 64;

    const int Klim = (it + 1) * 64;   // <= 1024

    float acc[4][4] = {};
    gemm_tile64<false>(A, TSEQ, Bm, EH, Klim, acc);

    const int tx = threadIdx.x & 15, ty = threadIdx.x >> 4;
    #pragma unroll
    for (int i = 0; i < 4; ++i) {
        int m = it * 64 + ty * 4 + i;
        #pragma unroll
        for (int j = 0; j < 4; ++j) {
            int n = tx * 4 + j;
            C[(size_t)m * EH + n] = acc[i][j];
        }
    }
}

// ---------------------------------------------------------------------------
// 5) Output projection: out[8192 x 256] = g_o[8192 x 2048] @ Wu + bu
//    grid = (4, 128)
// ---------------------------------------------------------------------------
__global__ __launch_bounds__(256)
void proj_kernel(const float* __restrict__ Wu, const float* __restrict__ bu,
                 float* __restrict__ out)
{
    const int col0 = blockIdx.x * 64;
    const int row0 = blockIdx.y * 64;

    float acc[4][4] = {};
    gemm_tile64<false>(g_o + (size_t)row0 * EH, EH, Wu + col0, EDIM, EH, acc);

    const int tx = threadIdx.x & 15, ty = threadIdx.x >> 4;
    #pragma unroll
    for (int i = 0; i < 4; ++i) {
        int m = row0 + ty * 4 + i;
        #pragma unroll
        for (int j = 0; j < 4; ++j) {
            int n = col0 + tx * 4 + j;
            out[(size_t)m * EDIM + n] = acc[i][j] + bu[n];
        }
    }
}

// ---------------------------------------------------------------------------
extern "C" void kernel_launch(void* const* d_in, const int* in_sizes, int n_in,
                              void* d_out, int out_size)
{
    (void)in_sizes; (void)n_in; (void)out_size;
    const float* x  = (const float*)d_in[0];
    const float* Wq = (const float*)d_in[1];
    const float* bq = (const float*)d_in[2];
    const float* Wk = (const float*)d_in[3];
    const float* bk = (const float*)d_in[4];
    const float* Wv = (const float*)d_in[5];
    const float* bv = (const float*)d_in[6];
    const float* Wu = (const float*)d_in[7];
    const float* bu = (const float*)d_in[8];
    float* out = (float*)d_out;

    dim3 blk(256);
    qkv_kernel<<<dim3(EH / 64, ROWS / 64, 3), blk>>>(x, Wq, bq, Wk, bk, Wv, bv);
    scores_kernel<<<dim3(16, 16, 64), blk>>>();
    softmax_kernel<<<dim3(64 * TSEQ), blk>>>();
    attnv_kernel<<<dim3(4, 16, 64), blk>>>();
    proj_kernel<<<dim3(EDIM / 64, ROWS / 64), blk>>>(Wu, bu, out);
}

// round 4
// speedup vs baseline: 2.8622x; 2.8622x over previous
#include <cuda_runtime.h>
#include <cstdint>

#define TSEQ 1024
#define EDIM 256
#define EH   2048
#define ROWS 8192

// ---------------- scratch (static device globals) ----------------
__device__ __align__(16) float g_q [ROWS * (size_t)EH];
__device__ __align__(16) float g_k [ROWS * (size_t)EH];
__device__ __align__(16) float g_v [ROWS * (size_t)EH];
__device__ __align__(16) float g_vt[64 * (size_t)EDIM * TSEQ];   // [bh][n][j]
__device__ __align__(16) float g_s [64LL * TSEQ * TSEQ];         // [bh][i][j]
__device__ __align__(16) float g_o [ROWS * (size_t)EH];
__device__ __align__(16) float g_wt[4 * (size_t)EH * EDIM];      // WqT,WkT,WvT [2048][256]; WuT [256][2048]

// ---------------- helpers ----------------
__device__ __forceinline__ uint32_t f2tf32(float f) {
    uint32_t u; asm("cvt.rna.tf32.f32 %0, %1;" : "=r"(u) : "f"(f)); return u;
}
__device__ __forceinline__ void mma_tf32_16n8k8(float* c, const uint32_t* a, const uint32_t* b) {
    asm volatile("mma.sync.aligned.m16n8k8.row.col.f32.tf32.tf32.f32 "
                 "{%0,%1,%2,%3}, {%4,%5,%6,%7}, {%8,%9}, {%0,%1,%2,%3};"
                 : "+f"(c[0]), "+f"(c[1]), "+f"(c[2]), "+f"(c[3])
                 : "r"(a[0]), "r"(a[1]), "r"(a[2]), "r"(a[3]), "r"(b[0]), "r"(b[1]));
}

// smem stage: 128 rows x 16 k-floats, padded row stride 20 floats (conflict-free frag reads)
#define SROW 20
#define SSTG (128 * SROW)   // floats per stage

__device__ __forceinline__ void ldg_stage(const float* __restrict__ A, int lda,
                                          const float* __restrict__ B, int ldb,
                                          int k0, float4 (&pa)[2], float4 (&pb)[2], int tid)
{
    #pragma unroll
    for (int u = 0; u < 2; ++u) {
        int id = tid + u * 256;                 // 0..511
        int row = id >> 2, f4 = id & 3;
        pa[u] = *(const float4*)(A + (size_t)row * lda + k0 + f4 * 4);
        pb[u] = *(const float4*)(B + (size_t)row * ldb + k0 + f4 * 4);
    }
}

__device__ __forceinline__ void sts_stage(float* As, float* Bs,
                                          const float4 (&pa)[2], const float4 (&pb)[2], int tid)
{
    #pragma unroll
    for (int u = 0; u < 2; ++u) {
        int id = tid + u * 256;
        int row = id >> 2, f4 = id & 3;
        uint4 ua = { f2tf32(pa[u].x), f2tf32(pa[u].y), f2tf32(pa[u].z), f2tf32(pa[u].w) };
        uint4 ub = { f2tf32(pb[u].x), f2tf32(pb[u].y), f2tf32(pb[u].z), f2tf32(pb[u].w) };
        *(uint4*)(As + row * SROW + f4 * 4) = ua;
        *(uint4*)(Bs + row * SROW + f4 * 4) = ub;
    }
}

__device__ __forceinline__ void compute_stage(const float* As, const float* Bs,
                                              float acc[2][8][4], int wm, int wn, int lane)
{
    #pragma unroll
    for (int ks = 0; ks < 2; ++ks) {
        const int kb = ks * 8 + (lane & 3);
        uint32_t af[2][4], bf[8][2];
        #pragma unroll
        for (int mt = 0; mt < 2; ++mt) {
            const float* p = As + (wm * 32 + mt * 16 + (lane >> 2)) * SROW + kb;
            af[mt][0] = __float_as_uint(p[0]);
            af[mt][1] = __float_as_uint(p[8 * SROW]);
            af[mt][2] = __float_as_uint(p[4]);
            af[mt][3] = __float_as_uint(p[8 * SROW + 4]);
        }
        #pragma unroll
        for (int nt = 0; nt < 8; ++nt) {
            const float* p = Bs + (wn * 64 + nt * 8 + (lane >> 2)) * SROW + kb;
            bf[nt][0] = __float_as_uint(p[0]);
            bf[nt][1] = __float_as_uint(p[4]);
        }
        #pragma unroll
        for (int mt = 0; mt < 2; ++mt)
            #pragma unroll
            for (int nt = 0; nt < 8; ++nt)
                mma_tf32_16n8k8(acc[mt][nt], af[mt], bf[nt]);
    }
}

// D[128x128] = A[128xK] . B[128xK]^T, both K-contiguous. K multiple of 16.
__device__ __forceinline__ void gemm_mma(const float* __restrict__ A, int lda,
                                         const float* __restrict__ B, int ldb,
                                         int K, float acc[2][8][4],
                                         float* As, float* Bs)
{
    const int tid = threadIdx.x;
    const int wid = tid >> 5, lane = tid & 31;
    const int wm = wid & 3, wn = wid >> 2;
    const int KC = K >> 4;
    float4 pa[2][2], pb[2][2];

    ldg_stage(A, lda, B, ldb, 0, pa[0], pb[0], tid);
    if (KC > 1) ldg_stage(A, lda, B, ldb, 16, pa[1], pb[1], tid);
    sts_stage(As, Bs, pa[0], pb[0], tid);
    __syncthreads();

    for (int c = 0; c < KC; ++c) {
        const int cur = c & 1;
        if (c + 1 < KC) sts_stage(As + ((c + 1) & 1) * SSTG, Bs + ((c + 1) & 1) * SSTG,
                                  pa[(c + 1) & 1], pb[(c + 1) & 1], tid);
        if (c + 2 < KC) ldg_stage(A, lda, B, ldb, (c + 2) * 16, pa[cur], pb[cur], tid);
        compute_stage(As + cur * SSTG, Bs + cur * SSTG, acc, wm, wn, lane);
        __syncthreads();
    }
}

// plain epilogue: C pre-offset to tile origin, optional bias (pre-offset to tile col0)
__device__ __forceinline__ void epi_plain(float acc[2][8][4], float* C, int ldc,
                                          const float* bias)
{
    const int wid = threadIdx.x >> 5, lane = threadIdx.x & 31;
    const int wm = wid & 3, wn = wid >> 2;
    #pragma unroll
    for (int mt = 0; mt < 2; ++mt) {
        const int m = wm * 32 + mt * 16 + (lane >> 2);
        #pragma unroll
        for (int nt = 0; nt < 8; ++nt) {
            const int n = wn * 64 + nt * 8 + (lane & 3) * 2;
            float b0 = 0.f, b1 = 0.f;
            if (bias) { b0 = bias[n]; b1 = bias[n + 1]; }
            *(float2*)(C + (size_t)m * ldc + n) =
                make_float2(acc[mt][nt][0] + b0, acc[mt][nt][1] + b1);
            *(float2*)(C + (size_t)(m + 8) * ldc + n) =
                make_float2(acc[mt][nt][2] + b0, acc[mt][nt][3] + b1);
        }
    }
}

// ---------------- kernels ----------------

// 0a) transpose weights
__global__ __launch_bounds__(256) void transpose_w(const float* __restrict__ Wq,
                                                   const float* __restrict__ Wk,
                                                   const float* __restrict__ Wv,
                                                   const float* __restrict__ Wu)
{
    const int z = blockIdx.z;
    const float* src; float* dst; int R, C;
    if (z < 3) { src = (z == 0) ? Wq : (z == 1) ? Wk : Wv; dst = g_wt + (size_t)z * 524288; R = EDIM; C = EH; }
    else       { src = Wu; dst = g_wt + 3 * 524288; R = EH; C = EDIM; }
    const int cb = blockIdx.x * 32, rb = blockIdx.y * 32;
    if (cb >= C || rb >= R) return;
    __shared__ float t[32][33];
    const int tx = threadIdx.x & 31, ty = threadIdx.x >> 5;
    #pragma unroll
    for (int i = ty; i < 32; i += 8)
        t[i][tx] = src[(size_t)(rb + i) * C + cb + tx];
    __syncthreads();
    #pragma unroll
    for (int i = ty; i < 32; i += 8)
        dst[(size_t)(cb + i) * R + rb + tx] = t[tx][i];
}

// 0b) transpose V: g_v[(b*1024+j)][h*256+hn] -> g_vt[(bh*256+hn)][j]
__global__ __launch_bounds__(256) void transpose_v()
{
    const int bh = blockIdx.z, b = bh >> 3, h = bh & 7;
    const int jb = blockIdx.x * 32, nb = blockIdx.y * 32;
    __shared__ float t[32][33];
    const int tx = threadIdx.x & 31, ty = threadIdx.x >> 5;
    const float* src = g_v + (size_t)(b * TSEQ + jb) * EH + h * EDIM + nb;
    #pragma unroll
    for (int i = ty; i < 32; i += 8)
        t[i][tx] = src[(size_t)i * EH + tx];
    __syncthreads();
    float* dst = g_vt + ((size_t)bh * EDIM + nb) * TSEQ + jb;
    #pragma unroll
    for (int i = ty; i < 32; i += 8)
        dst[(size_t)i * TSEQ + tx] = t[tx][i];
}

// 1) QKV: [8192x2048] = x @ W + b
__global__ __launch_bounds__(256) void qkv_gemm(const float* __restrict__ x,
                                                const float* __restrict__ bq,
                                                const float* __restrict__ bk,
                                                const float* __restrict__ bv)
{
    __shared__ __align__(16) float As[2 * SSTG], Bs[2 * SSTG];
    const int z = blockIdx.z, col0 = blockIdx.x * 128, row0 = blockIdx.y * 128;
    const float* A = x + (size_t)row0 * EDIM;
    const float* B = g_wt + (size_t)z * 524288 + (size_t)col0 * EDIM;
    float acc[2][8][4] = {};
    gemm_mma(A, EDIM, B, EDIM, EDIM, acc, As, Bs);
    float* C = (z == 0 ? g_q : z == 1 ? g_k : g_v) + (size_t)row0 * EH + col0;
    const float* bias = (z == 0 ? bq : z == 1 ? bk : bv) + col0;
    epi_plain(acc, C, EH, bias);
}

// 2) scores: S = Q.K^T/16 masked j<i, tiles jt<=it
__global__ __launch_bounds__(256) void scores_gemm()
{
    const int jt = blockIdx.x, it = blockIdx.y, bh = blockIdx.z;
    if (jt > it) return;
    __shared__ __align__(16) float As[2 * SSTG], Bs[2 * SSTG];
    const int b = bh >> 3, h = bh & 7;
    const float* A = g_q + (size_t)(b * TSEQ + it * 128) * EH + h * EDIM;
    const float* B = g_k + (size_t)(b * TSEQ + jt * 128) * EH + h * EDIM;
    float acc[2][8][4] = {};
    gemm_mma(A, EH, B, EH, EDIM, acc, As, Bs);

    float* C = g_s + ((size_t)bh << 20) + (size_t)(it * 128) * TSEQ + jt * 128;
    const int wid = threadIdx.x >> 5, lane = threadIdx.x & 31;
    const int wm = wid & 3, wn = wid >> 2;
    const int gi0 = it * 128, gj0 = jt * 128;
    const bool full = (jt < it);
    #pragma unroll
    for (int mt = 0; mt < 2; ++mt) {
        const int m = wm * 32 + mt * 16 + (lane >> 2);
        #pragma unroll
        for (int nt = 0; nt < 8; ++nt) {
            const int n = wn * 64 + nt * 8 + (lane & 3) * 2;
            float v0 = acc[mt][nt][0] * 0.0625f, v1 = acc[mt][nt][1] * 0.0625f;
            float v2 = acc[mt][nt][2] * 0.0625f, v3 = acc[mt][nt][3] * 0.0625f;
            if (full) {
                *(float2*)(C + (size_t)m * TSEQ + n) = make_float2(v0, v1);
                *(float2*)(C + (size_t)(m + 8) * TSEQ + n) = make_float2(v2, v3);
            } else {
                const int gj = gj0 + n;
                int gi = gi0 + m;
                if (gj < gi)     C[(size_t)m * TSEQ + n]     = v0;
                if (gj + 1 < gi) C[(size_t)m * TSEQ + n + 1] = v1;
                gi += 8;
                if (gj < gi)     C[(size_t)(m + 8) * TSEQ + n]     = v2;
                if (gj + 1 < gi) C[(size_t)(m + 8) * TSEQ + n + 1] = v3;
            }
        }
    }
}

// 3) softmax rows of g_s; fill zeros only up to the 128-tile boundary needed by attnv
__global__ __launch_bounds__(256) void softmax_kernel()
{
    const int row = blockIdx.x;
    const int i = row & (TSEQ - 1);
    float* p = g_s + (size_t)row * TSEQ;
    const int tid = threadIdx.x;
    const int klim = ((i >> 7) + 1) << 7;

    if (i == 0) { for (int j = tid; j < klim; j += 256) p[j] = 0.f; return; }

    __shared__ float red[8];
    const int lane = tid & 31, wid = tid >> 5;

    float m = -3.0e38f;
    for (int j = tid; j < i; j += 256) m = fmaxf(m, p[j]);
    #pragma unroll
    for (int s = 16; s > 0; s >>= 1) m = fmaxf(m, __shfl_xor_sync(0xffffffffu, m, s));
    if (lane == 0) red[wid] = m;
    __syncthreads();
    m = red[lane & 7];
    #pragma unroll
    for (int s = 4; s > 0; s >>= 1) m = fmaxf(m, __shfl_xor_sync(0xffffffffu, m, s));

    float sum = 0.f;
    for (int j = tid; j < i; j += 256) sum += __expf(p[j] - m);
    #pragma unroll
    for (int s = 16; s > 0; s >>= 1) sum += __shfl_xor_sync(0xffffffffu, sum, s);
    __syncthreads();
    if (lane == 0) red[wid] = sum;
    __syncthreads();
    sum = red[lane & 7];
    #pragma unroll
    for (int s = 4; s > 0; s >>= 1) sum += __shfl_xor_sync(0xffffffffu, sum, s);
    const float inv = 1.0f / sum;

    for (int j = tid; j < klim; j += 256)
        p[j] = (j < i) ? __expf(p[j] - m) * inv : 0.f;
}

// 4) attnv: O = P @ Vt^T, K clipped to (it+1)*128
__global__ __launch_bounds__(256) void attnv_gemm()
{
    const int nt = blockIdx.x, it = blockIdx.y, bh = blockIdx.z;
    __shared__ __align__(16) float As[2 * SSTG], Bs[2 * SSTG];
    const int b = bh >> 3, h = bh & 7;
    const float* A = g_s + ((size_t)bh << 20) + (size_t)(it * 128) * TSEQ;
    const float* B = g_vt + ((size_t)bh * EDIM + nt * 128) * TSEQ;
    float acc[2][8][4] = {};
    gemm_mma(A, TSEQ, B, TSEQ, (it + 1) * 128, acc, As, Bs);
    float* C = g_o + (size_t)(b * TSEQ + it * 128) * EH + h * EDIM + nt * 128;
    epi_plain(acc, C, EH, nullptr);
}

// 5) proj: out = g_o @ Wu + bu
__global__ __launch_bounds__(256) void proj_gemm(const float* __restrict__ bu,
                                                 float* __restrict__ out)
{
    const int col0 = blockIdx.x * 128, row0 = blockIdx.y * 128;
    __shared__ __align__(16) float As[2 * SSTG], Bs[2 * SSTG];
    const float* A = g_o + (size_t)row0 * EH;
    const float* B = g_wt + 3 * 524288 + (size_t)col0 * EH;
    float acc[2][8][4] = {};
    gemm_mma(A, EH, B, EH, EH, acc, As, Bs);
    epi_plain(acc, out + (size_t)row0 * EDIM + col0, EDIM, bu + col0);
}

// ---------------------------------------------------------------------------
extern "C" void kernel_launch(void* const* d_in, const int* in_sizes, int n_in,
                              void* d_out, int out_size)
{
    (void)in_sizes; (void)n_in; (void)out_size;
    const float* x  = (const float*)d_in[0];
    const float* Wq = (const float*)d_in[1];
    const float* bq = (const float*)d_in[2];
    const float* Wk = (const float*)d_in[3];
    const float* bk = (const float*)d_in[4];
    const float* Wv = (const float*)d_in[5];
    const float* bv = (const float*)d_in[6];
    const float* Wu = (const float*)d_in[7];
    const float* bu = (const float*)d_in[8];
    float* out = (float*)d_out;

    dim3 blk(256);
    transpose_w   <<<dim3(64, 64, 4), blk>>>(Wq, Wk, Wv, Wu);
    qkv_gemm      <<<dim3(16, 64, 3), blk>>>(x, bq, bk, bv);
    transpose_v   <<<dim3(32, 8, 64), blk>>>();
    scores_gemm   <<<dim3(8, 8, 64), blk>>>();
    softmax_kernel<<<dim3(64 * TSEQ), blk>>>();
    attnv_gemm    <<<dim3(2, 8, 64), blk>>>();
    proj_gemm     <<<dim3(2, 64, 1), blk>>>(bu, out);
}

// round 5
// speedup vs baseline: 5.2459x; 1.8328x over previous
#include <cuda_runtime.h>
#include <cstdint>

#define TSEQ 1024
#define EDIM 256
#define EH   2048
#define ROWS 8192

// ---------------- scratch ----------------
__device__ __align__(16) float g_xr[ROWS * (size_t)EDIM];        // tf32-rounded x
__device__ __align__(16) float g_q [ROWS * (size_t)EH];
__device__ __align__(16) float g_k [ROWS * (size_t)EH];
__device__ __align__(16) float g_v [ROWS * (size_t)EH];
__device__ __align__(16) float g_vt[64 * (size_t)EDIM * TSEQ];   // [bh][n][j]
__device__ __align__(16) float g_s [64LL * TSEQ * TSEQ];         // [bh][i][j]
__device__ __align__(16) float g_o [ROWS * (size_t)EH];
__device__ __align__(16) float g_wt[4 * (size_t)EH * EDIM];      // WqT,WkT,WvT,WuT (K-contig)

// ---------------- helpers ----------------
__device__ __forceinline__ float f2tf32f(float f) {
    uint32_t u; asm("cvt.rna.tf32.f32 %0, %1;" : "=r"(u) : "f"(f));
    return __uint_as_float(u);
}
__device__ __forceinline__ uint32_t smem_u32(const void* p) {
    uint32_t a;
    asm("{ .reg .u64 t; cvta.to.shared.u64 t, %1; cvt.u32.u64 %0, t; }" : "=r"(a) : "l"(p));
    return a;
}
__device__ __forceinline__ void mma_tf32(float* c, const uint32_t* a, const uint32_t* b) {
    asm volatile("mma.sync.aligned.m16n8k8.row.col.f32.tf32.tf32.f32 "
                 "{%0,%1,%2,%3}, {%4,%5,%6,%7}, {%8,%9}, {%0,%1,%2,%3};"
                 : "+f"(c[0]), "+f"(c[1]), "+f"(c[2]), "+f"(c[3])
                 : "r"(a[0]), "r"(a[1]), "r"(a[2]), "r"(a[3]), "r"(b[0]), "r"(b[1]));
}
#define LDSM_X4(r0, r1, r2, r3, addr) \
    asm volatile("ldmatrix.sync.aligned.m8n8.x4.shared.b16 {%0,%1,%2,%3}, [%4];" \
                 : "=r"(r0), "=r"(r1), "=r"(r2), "=r"(r3) : "r"(addr))
#define CP16(dst, src) \
    asm volatile("cp.async.cg.shared.global [%0], [%1], 16;" :: "r"(dst), "l"(src))
#define CP_COMMIT()  asm volatile("cp.async.commit_group;")
#define CP_WAIT1()   asm volatile("cp.async.wait_group 1;")
#define CP_WAIT0()   asm volatile("cp.async.wait_group 0;")

// smem tile: 128 rows x 64 B (16 tf32), XOR-swizzled so every 8-row ldmatrix
// read and every cp.async store wave is bank-conflict-free.
__device__ __forceinline__ uint32_t swad(int row, int cb) {
    return (uint32_t)(row * 64 + (cb ^ (((row >> 1) & 3) << 4)));
}

#define STAGES    3
#define STAGE_B   16384            // A tile 8 KB + B tile 8 KB
#define SMEM_BYTES (STAGES * STAGE_B)

// issue one k-stage (BK=16) of A and B via cp.async (128 threads)
__device__ __forceinline__ void issue_stage(uint32_t sb, int s,
                                            const float* __restrict__ A, int lda,
                                            const float* __restrict__ B, int ldb,
                                            int k0, int tid)
{
    const uint32_t abase = sb + s * STAGE_B;
    const uint32_t bbase = abase + 8192;
    const int r0 = tid >> 2;
    const int cb = (tid & 3) << 4;
    const float* asrc = A + (size_t)r0 * lda + k0 + (tid & 3) * 4;
    const float* bsrc = B + (size_t)r0 * ldb + k0 + (tid & 3) * 4;
    #pragma unroll
    for (int w = 0; w < 4; ++w) {
        const int row = w * 32 + r0;
        CP16(abase + swad(row, cb), asrc + (size_t)w * 32 * lda);
        CP16(bbase + swad(row, cb), bsrc + (size_t)w * 32 * ldb);
    }
    CP_COMMIT();
}

// compute one k-stage: warp tile 64x64, frags via ldmatrix.x4
__device__ __forceinline__ void compute_stage(uint32_t sb, int s, float acc[4][8][4],
                                              int wm, int wn, int lane)
{
    const uint32_t abase = sb + s * STAGE_B;
    const uint32_t bbase = abase + 8192;

    // B frags: 8 n-tiles, each x4 = {b0 ks0, b1 ks0, b0 ks1, b1 ks1}
    uint32_t bf[8][4];
    {
        const int brow = wn * 64 + (lane & 7);
        const uint32_t bcb = (uint32_t)((lane >> 3) << 4);
        const uint32_t bsw = (uint32_t)((((lane & 7) >> 1) & 3) << 4);
        #pragma unroll
        for (int nt = 0; nt < 8; ++nt) {
            uint32_t ad = bbase + (uint32_t)((brow + nt * 8) * 64) + (bcb ^ bsw);
            LDSM_X4(bf[nt][0], bf[nt][1], bf[nt][2], bf[nt][3], ad);
        }
    }
    const int arow = wm * 64 + (lane & 15);
    const uint32_t ahi = (lane >= 16) ? 16u : 0u;
    const uint32_t asw = (uint32_t)((((lane & 15) >> 1) & 3) << 4);

    #pragma unroll
    for (int ks = 0; ks < 2; ++ks) {
        uint32_t af[4][4];
        #pragma unroll
        for (int mt = 0; mt < 4; ++mt) {
            uint32_t ad = abase + (uint32_t)((arow + mt * 16) * 64)
                        + (((uint32_t)(ks * 32) + ahi) ^ asw);
            LDSM_X4(af[mt][0], af[mt][1], af[mt][2], af[mt][3], ad);
        }
        #pragma unroll
        for (int mt = 0; mt < 4; ++mt)
            #pragma unroll
            for (int nt = 0; nt < 8; ++nt)
                mma_tf32(acc[mt][nt], af[mt], &bf[nt][ks * 2]);
    }
}

// D[128x128] = A[128xK] . B[128xK]^T (both K-contiguous, tf32-pre-rounded)
__device__ __forceinline__ void gemm_mma(const float* __restrict__ A, int lda,
                                         const float* __restrict__ B, int ldb,
                                         int K, float acc[4][8][4], uint32_t sb)
{
    const int tid = threadIdx.x;
    const int wid = tid >> 5, lane = tid & 31;
    const int wm = wid & 1, wn = wid >> 1;
    const int KC = K >> 4;

    issue_stage(sb, 0, A, lda, B, ldb, 0, tid);
    if (KC > 1) issue_stage(sb, 1, A, lda, B, ldb, 16, tid);

    int s = 0;
    for (int c = 0; c < KC; ++c) {
        if (c + 2 < KC) CP_WAIT1(); else CP_WAIT0();
        __syncthreads();
        if (c + 2 < KC) {
            int ns = s + 2; if (ns >= STAGES) ns -= STAGES;
            issue_stage(sb, ns, A, lda, B, ldb, (c + 2) * 16, tid);
        }
        compute_stage(sb, s, acc, wm, wn, lane);
        if (++s == STAGES) s = 0;
        __syncthreads();
    }
}

// epilogue: ROUND=1 -> tf32-round stored values. C pre-offset to tile origin.
template<int ROUND>
__device__ __forceinline__ void epi_plain(float acc[4][8][4], float* C, int ldc,
                                          const float* bias)
{
    const int wid = threadIdx.x >> 5, lane = threadIdx.x & 31;
    const int wm = wid & 1, wn = wid >> 1;
    #pragma unroll
    for (int mt = 0; mt < 4; ++mt) {
        const int m = wm * 64 + mt * 16 + (lane >> 2);
        #pragma unroll
        for (int nt = 0; nt < 8; ++nt) {
            const int n = wn * 64 + nt * 8 + (lane & 3) * 2;
            float b0 = 0.f, b1 = 0.f;
            if (bias) { b0 = bias[n]; b1 = bias[n + 1]; }
            float v0 = acc[mt][nt][0] + b0, v1 = acc[mt][nt][1] + b1;
            float v2 = acc[mt][nt][2] + b0, v3 = acc[mt][nt][3] + b1;
            if (ROUND) { v0 = f2tf32f(v0); v1 = f2tf32f(v1); v2 = f2tf32f(v2); v3 = f2tf32f(v3); }
            *(float2*)(C + (size_t)m * ldc + n)       = make_float2(v0, v1);
            *(float2*)(C + (size_t)(m + 8) * ldc + n) = make_float2(v2, v3);
        }
    }
}

// ---------------- kernels ----------------

// 0a) round x to tf32 (float4 elementwise)
__global__ __launch_bounds__(256) void round_x(const float* __restrict__ x)
{
    const size_t i = ((size_t)blockIdx.x * 256 + threadIdx.x) * 4;
    float4 v = *(const float4*)(x + i);
    v.x = f2tf32f(v.x); v.y = f2tf32f(v.y); v.z = f2tf32f(v.z); v.w = f2tf32f(v.w);
    *(float4*)(g_xr + i) = v;
}

// 0b) transpose + round weights
__global__ __launch_bounds__(256) void transpose_w(const float* __restrict__ Wq,
                                                   const float* __restrict__ Wk,
                                                   const float* __restrict__ Wv,
                                                   const float* __restrict__ Wu)
{
    const int z = blockIdx.z;
    const float* src; float* dst; int R, C;
    if (z < 3) { src = (z == 0) ? Wq : (z == 1) ? Wk : Wv; dst = g_wt + (size_t)z * 524288; R = EDIM; C = EH; }
    else       { src = Wu; dst = g_wt + 3 * 524288; R = EH; C = EDIM; }
    const int cb = blockIdx.x * 32, rb = blockIdx.y * 32;
    if (cb >= C || rb >= R) return;
    __shared__ float t[32][33];
    const int tx = threadIdx.x & 31, ty = threadIdx.x >> 5;
    #pragma unroll
    for (int i = ty; i < 32; i += 8)
        t[i][tx] = f2tf32f(src[(size_t)(rb + i) * C + cb + tx]);
    __syncthreads();
    #pragma unroll
    for (int i = ty; i < 32; i += 8)
        dst[(size_t)(cb + i) * R + rb + tx] = t[tx][i];
}

// 0c) transpose V (already rounded by qkv epilogue)
__global__ __launch_bounds__(256) void transpose_v()
{
    const int bh = blockIdx.z, b = bh >> 3, h = bh & 7;
    const int jb = blockIdx.x * 32, nb = blockIdx.y * 32;
    __shared__ float t[32][33];
    const int tx = threadIdx.x & 31, ty = threadIdx.x >> 5;
    const float* src = g_v + (size_t)(b * TSEQ + jb) * EH + h * EDIM + nb;
    #pragma unroll
    for (int i = ty; i < 32; i += 8)
        t[i][tx] = src[(size_t)i * EH + tx];
    __syncthreads();
    float* dst = g_vt + ((size_t)bh * EDIM + nb) * TSEQ + jb;
    #pragma unroll
    for (int i = ty; i < 32; i += 8)
        dst[(size_t)i * TSEQ + tx] = t[tx][i];
}

// 1) QKV
__global__ __launch_bounds__(128) void qkv_gemm(const float* __restrict__ bq,
                                                const float* __restrict__ bk,
                                                const float* __restrict__ bv)
{
    __shared__ __align__(1024) unsigned char sbuf[SMEM_BYTES];
    const uint32_t sb = smem_u32(sbuf);
    const int z = blockIdx.z, col0 = blockIdx.x * 128, row0 = blockIdx.y * 128;
    const float* A = g_xr + (size_t)row0 * EDIM;
    const float* B = g_wt + (size_t)z * 524288 + (size_t)col0 * EDIM;
    float acc[4][8][4] = {};
    gemm_mma(A, EDIM, B, EDIM, EDIM, acc, sb);
    float* C = (z == 0 ? g_q : z == 1 ? g_k : g_v) + (size_t)row0 * EH + col0;
    const float* bias = (z == 0 ? bq : z == 1 ? bk : bv) + col0;
    epi_plain<1>(acc, C, EH, bias);           // rounded: feeds later GEMMs
}

// 2) scores (masked j<i, tiles jt<=it, scale 1/16; fp32 store for softmax)
__global__ __launch_bounds__(128) void scores_gemm()
{
    const int jt = blockIdx.x, it = blockIdx.y, bh = blockIdx.z;
    if (jt > it) return;
    __shared__ __align__(1024) unsigned char sbuf[SMEM_BYTES];
    const uint32_t sb = smem_u32(sbuf);
    const int b = bh >> 3, h = bh & 7;
    const float* A = g_q + (size_t)(b * TSEQ + it * 128) * EH + h * EDIM;
    const float* B = g_k + (size_t)(b * TSEQ + jt * 128) * EH + h * EDIM;
    float acc[4][8][4] = {};
    gemm_mma(A, EH, B, EH, EDIM, acc, sb);

    float* C = g_s + ((size_t)bh << 20) + (size_t)(it * 128) * TSEQ + jt * 128;
    const int wid = threadIdx.x >> 5, lane = threadIdx.x & 31;
    const int wm = wid & 1, wn = wid >> 1;
    const bool full = (jt < it);
    #pragma unroll
    for (int mt = 0; mt < 4; ++mt) {
        const int m = wm * 64 + mt * 16 + (lane >> 2);
        #pragma unroll
        for (int nt = 0; nt < 8; ++nt) {
            const int n = wn * 64 + nt * 8 + (lane & 3) * 2;
            float v0 = acc[mt][nt][0] * 0.0625f, v1 = acc[mt][nt][1] * 0.0625f;
            float v2 = acc[mt][nt][2] * 0.0625f, v3 = acc[mt][nt][3] * 0.0625f;
            if (full) {
                *(float2*)(C + (size_t)m * TSEQ + n)       = make_float2(v0, v1);
                *(float2*)(C + (size_t)(m + 8) * TSEQ + n) = make_float2(v2, v3);
            } else {                 // diagonal tile: local mask n<m
                if (n < m)          C[(size_t)m * TSEQ + n]           = v0;
                if (n + 1 < m)      C[(size_t)m * TSEQ + n + 1]       = v1;
                if (n < m + 8)      C[(size_t)(m + 8) * TSEQ + n]     = v2;
                if (n + 1 < m + 8)  C[(size_t)(m + 8) * TSEQ + n + 1] = v3;
            }
        }
    }
}

// 3) softmax rows; writes tf32-rounded P, zero-fills to 128-tile boundary
__global__ __launch_bounds__(256) void softmax_kernel()
{
    const int row = blockIdx.x;
    const int i = row & (TSEQ - 1);
    float* p = g_s + (size_t)row * TSEQ;
    const int tid = threadIdx.x;
    const int klim = ((i >> 7) + 1) << 7;

    if (i == 0) { for (int j = tid; j < klim; j += 256) p[j] = 0.f; return; }

    __shared__ float red[8];
    const int lane = tid & 31, wid = tid >> 5;

    float m = -3.0e38f;
    for (int j = tid; j < i; j += 256) m = fmaxf(m, p[j]);
    #pragma unroll
    for (int s = 16; s > 0; s >>= 1) m = fmaxf(m, __shfl_xor_sync(0xffffffffu, m, s));
    if (lane == 0) red[wid] = m;
    __syncthreads();
    m = red[lane & 7];
    #pragma unroll
    for (int s = 4; s > 0; s >>= 1) m = fmaxf(m, __shfl_xor_sync(0xffffffffu, m, s));

    float sum = 0.f;
    for (int j = tid; j < i; j += 256) sum += __expf(p[j] - m);
    #pragma unroll
    for (int s = 16; s > 0; s >>= 1) sum += __shfl_xor_sync(0xffffffffu, sum, s);
    __syncthreads();
    if (lane == 0) red[wid] = sum;
    __syncthreads();
    sum = red[lane & 7];
    #pragma unroll
    for (int s = 4; s > 0; s >>= 1) sum += __shfl_xor_sync(0xffffffffu, sum, s);
    const float inv = 1.0f / sum;

    for (int j = tid; j < klim; j += 256)
        p[j] = (j < i) ? f2tf32f(__expf(p[j] - m) * inv) : 0.f;
}

// 4) attnv (K clipped)
__global__ __launch_bounds__(128) void attnv_gemm()
{
    const int nt = blockIdx.x, it = blockIdx.y, bh = blockIdx.z;
    __shared__ __align__(1024) unsigned char sbuf[SMEM_BYTES];
    const uint32_t sb = smem_u32(sbuf);
    const int b = bh >> 3, h = bh & 7;
    const float* A = g_s + ((size_t)bh << 20) + (size_t)(it * 128) * TSEQ;
    const float* B = g_vt + ((size_t)bh * EDIM + nt * 128) * TSEQ;
    float acc[4][8][4] = {};
    gemm_mma(A, TSEQ, B, TSEQ, (it + 1) * 128, acc, sb);
    float* C = g_o + (size_t)(b * TSEQ + it * 128) * EH + h * EDIM + nt * 128;
    epi_plain<1>(acc, C, EH, nullptr);        // rounded: feeds proj
}

// 5) proj (fp32 store)
__global__ __launch_bounds__(128) void proj_gemm(const float* __restrict__ bu,
                                                 float* __restrict__ out)
{
    const int col0 = blockIdx.x * 128, row0 = blockIdx.y * 128;
    __shared__ __align__(1024) unsigned char sbuf[SMEM_BYTES];
    const uint32_t sb = smem_u32(sbuf);
    const float* A = g_o + (size_t)row0 * EH;
    const float* B = g_wt + 3 * 524288 + (size_t)col0 * EH;
    float acc[4][8][4] = {};
    gemm_mma(A, EH, B, EH, EH, acc, sb);
    epi_plain<0>(acc, out + (size_t)row0 * EDIM + col0, EDIM, bu + col0);
}

// ---------------------------------------------------------------------------
extern "C" void kernel_launch(void* const* d_in, const int* in_sizes, int n_in,
                              void* d_out, int out_size)
{
    (void)in_sizes; (void)n_in; (void)out_size;
    const float* x  = (const float*)d_in[0];
    const float* Wq = (const float*)d_in[1];
    const float* bq = (const float*)d_in[2];
    const float* Wk = (const float*)d_in[3];
    const float* bk = (const float*)d_in[4];
    const float* Wv = (const float*)d_in[5];
    const float* bv = (const float*)d_in[6];
    const float* Wu = (const float*)d_in[7];
    const float* bu = (const float*)d_in[8];
    float* out = (float*)d_out;

    round_x       <<<dim3(ROWS * EDIM / 1024), 256>>>(x);
    transpose_w   <<<dim3(64, 64, 4), 256>>>(Wq, Wk, Wv, Wu);
    qkv_gemm      <<<dim3(16, 64, 3), 128>>>(bq, bk, bv);
    transpose_v   <<<dim3(32, 8, 64), 256>>>();
    scores_gemm   <<<dim3(8, 8, 64), 128>>>();
    softmax_kernel<<<dim3(64 * TSEQ), 256>>>();
    attnv_gemm    <<<dim3(2, 8, 64), 128>>>();
    proj_gemm     <<<dim3(2, 64, 1), 128>>>(bu, out);
}

// round 6
// speedup vs baseline: 6.2785x; 1.1968x over previous
#include <cuda_runtime.h>
#include <cstdint>

#define TSEQ 1024
#define EDIM 256
#define EH   2048
#define ROWS 8192

// ---------------- scratch ----------------
__device__ __align__(16) float g_xr[ROWS * (size_t)EDIM];        // tf32-rounded x
__device__ __align__(16) float g_q [ROWS * (size_t)EH];
__device__ __align__(16) float g_k [ROWS * (size_t)EH];
__device__ __align__(16) float g_vt[64 * (size_t)EDIM * TSEQ];   // [bh][n][j] (tf32-rounded)
__device__ __align__(16) float g_s [64LL * TSEQ * TSEQ];         // [bh][i][j] = exp(s/16) unnormalized
__device__ __align__(16) float g_rsum[64 * TSEQ];                // row sums of g_s
__device__ __align__(16) float g_o [ROWS * (size_t)EH];
__device__ __align__(16) float g_wt[4 * (size_t)EH * EDIM];      // WqT,WkT,WvT,WuT (K-contig)

// ---------------- helpers ----------------
__device__ __forceinline__ float f2tf32f(float f) {
    uint32_t u; asm("cvt.rna.tf32.f32 %0, %1;" : "=r"(u) : "f"(f));
    return __uint_as_float(u);
}
__device__ __forceinline__ uint32_t smem_u32(const void* p) {
    uint32_t a;
    asm("{ .reg .u64 t; cvta.to.shared.u64 t, %1; cvt.u32.u64 %0, t; }" : "=r"(a) : "l"(p));
    return a;
}
__device__ __forceinline__ void mma_tf32(float* c, const uint32_t* a, const uint32_t* b) {
    asm volatile("mma.sync.aligned.m16n8k8.row.col.f32.tf32.tf32.f32 "
                 "{%0,%1,%2,%3}, {%4,%5,%6,%7}, {%8,%9}, {%0,%1,%2,%3};"
                 : "+f"(c[0]), "+f"(c[1]), "+f"(c[2]), "+f"(c[3])
                 : "r"(a[0]), "r"(a[1]), "r"(a[2]), "r"(a[3]), "r"(b[0]), "r"(b[1]));
}
#define LDSM_X4(r0, r1, r2, r3, addr) \
    asm volatile("ldmatrix.sync.aligned.m8n8.x4.shared.b16 {%0,%1,%2,%3}, [%4];" \
                 : "=r"(r0), "=r"(r1), "=r"(r2), "=r"(r3) : "r"(addr))
#define CP16(dst, src) \
    asm volatile("cp.async.cg.shared.global [%0], [%1], 16;" :: "r"(dst), "l"(src))
#define CP_COMMIT()  asm volatile("cp.async.commit_group;")
#define CP_WAIT1()   asm volatile("cp.async.wait_group 1;")
#define CP_WAIT0()   asm volatile("cp.async.wait_group 0;")

// smem tile: 128 rows x 64 B (16 tf32), XOR-swizzled (conflict-free ldmatrix + cp.async)
__device__ __forceinline__ uint32_t swad(int row, int cb) {
    return (uint32_t)(row * 64 + (cb ^ (((row >> 1) & 3) << 4)));
}

#define STAGES    3
#define STAGE_B   16384
#define SMEM_BYTES (STAGES * STAGE_B)

__device__ __forceinline__ void issue_stage(uint32_t sb, int s,
                                            const float* __restrict__ A, int lda,
                                            const float* __restrict__ B, int ldb,
                                            int k0, int tid)
{
    const uint32_t abase = sb + s * STAGE_B;
    const uint32_t bbase = abase + 8192;
    const int r0 = tid >> 2;
    const int cb = (tid & 3) << 4;
    const float* asrc = A + (size_t)r0 * lda + k0 + (tid & 3) * 4;
    const float* bsrc = B + (size_t)r0 * ldb + k0 + (tid & 3) * 4;
    #pragma unroll
    for (int w = 0; w < 4; ++w) {
        const int row = w * 32 + r0;
        CP16(abase + swad(row, cb), asrc + (size_t)w * 32 * lda);
        CP16(bbase + swad(row, cb), bsrc + (size_t)w * 32 * ldb);
    }
    CP_COMMIT();
}

__device__ __forceinline__ void compute_stage(uint32_t sb, int s, float acc[4][8][4],
                                              int wm, int wn, int lane)
{
    const uint32_t abase = sb + s * STAGE_B;
    const uint32_t bbase = abase + 8192;

    uint32_t bf[8][4];
    {
        const int brow = wn * 64 + (lane & 7);
        const uint32_t bcb = (uint32_t)((lane >> 3) << 4);
        const uint32_t bsw = (uint32_t)((((lane & 7) >> 1) & 3) << 4);
        #pragma unroll
        for (int nt = 0; nt < 8; ++nt) {
            uint32_t ad = bbase + (uint32_t)((brow + nt * 8) * 64) + (bcb ^ bsw);
            LDSM_X4(bf[nt][0], bf[nt][1], bf[nt][2], bf[nt][3], ad);
        }
    }
    const int arow = wm * 64 + (lane & 15);
    const uint32_t ahi = (lane >= 16) ? 16u : 0u;
    const uint32_t asw = (uint32_t)((((lane & 15) >> 1) & 3) << 4);

    #pragma unroll
    for (int ks = 0; ks < 2; ++ks) {
        uint32_t af[4][4];
        #pragma unroll
        for (int mt = 0; mt < 4; ++mt) {
            uint32_t ad = abase + (uint32_t)((arow + mt * 16) * 64)
                        + (((uint32_t)(ks * 32) + ahi) ^ asw);
            LDSM_X4(af[mt][0], af[mt][1], af[mt][2], af[mt][3], ad);
        }
        #pragma unroll
        for (int mt = 0; mt < 4; ++mt)
            #pragma unroll
            for (int nt = 0; nt < 8; ++nt)
                mma_tf32(acc[mt][nt], af[mt], &bf[nt][ks * 2]);
    }
}

// D[128x128] = A[128xK] . B[128xK]^T
__device__ __forceinline__ void gemm_mma(const float* __restrict__ A, int lda,
                                         const float* __restrict__ B, int ldb,
                                         int K, float acc[4][8][4], uint32_t sb)
{
    const int tid = threadIdx.x;
    const int wid = tid >> 5, lane = tid & 31;
    const int wm = wid & 1, wn = wid >> 1;
    const int KC = K >> 4;

    issue_stage(sb, 0, A, lda, B, ldb, 0, tid);
    if (KC > 1) issue_stage(sb, 1, A, lda, B, ldb, 16, tid);

    int s = 0;
    for (int c = 0; c < KC; ++c) {
        if (c + 2 < KC) CP_WAIT1(); else CP_WAIT0();
        __syncthreads();
        if (c + 2 < KC) {
            int ns = s + 2; if (ns >= STAGES) ns -= STAGES;
            issue_stage(sb, ns, A, lda, B, ldb, (c + 2) * 16, tid);
        }
        compute_stage(sb, s, acc, wm, wn, lane);
        if (++s == STAGES) s = 0;
        __syncthreads();
    }
}

template<int ROUND>
__device__ __forceinline__ void epi_plain(float acc[4][8][4], float* C, int ldc,
                                          const float* bias)
{
    const int wid = threadIdx.x >> 5, lane = threadIdx.x & 31;
    const int wm = wid & 1, wn = wid >> 1;
    #pragma unroll
    for (int mt = 0; mt < 4; ++mt) {
        const int m = wm * 64 + mt * 16 + (lane >> 2);
        #pragma unroll
        for (int nt = 0; nt < 8; ++nt) {
            const int n = wn * 64 + nt * 8 + (lane & 3) * 2;
            float b0 = 0.f, b1 = 0.f;
            if (bias) { b0 = bias[n]; b1 = bias[n + 1]; }
            float v0 = acc[mt][nt][0] + b0, v1 = acc[mt][nt][1] + b1;
            float v2 = acc[mt][nt][2] + b0, v3 = acc[mt][nt][3] + b1;
            if (ROUND) { v0 = f2tf32f(v0); v1 = f2tf32f(v1); v2 = f2tf32f(v2); v3 = f2tf32f(v3); }
            *(float2*)(C + (size_t)m * ldc + n)       = make_float2(v0, v1);
            *(float2*)(C + (size_t)(m + 8) * ldc + n) = make_float2(v2, v3);
        }
    }
}

// ---------------- kernels ----------------

__global__ __launch_bounds__(256) void round_x(const float* __restrict__ x)
{
    const size_t i = ((size_t)blockIdx.x * 256 + threadIdx.x) * 4;
    float4 v = *(const float4*)(x + i);
    v.x = f2tf32f(v.x); v.y = f2tf32f(v.y); v.z = f2tf32f(v.z); v.w = f2tf32f(v.w);
    *(float4*)(g_xr + i) = v;
}

__global__ __launch_bounds__(256) void transpose_w(const float* __restrict__ Wq,
                                                   const float* __restrict__ Wk,
                                                   const float* __restrict__ Wv,
                                                   const float* __restrict__ Wu)
{
    const int z = blockIdx.z;
    const float* src; float* dst; int R, C;
    if (z < 3) { src = (z == 0) ? Wq : (z == 1) ? Wk : Wv; dst = g_wt + (size_t)z * 524288; R = EDIM; C = EH; }
    else       { src = Wu; dst = g_wt + 3 * 524288; R = EH; C = EDIM; }
    const int cb = blockIdx.x * 32, rb = blockIdx.y * 32;
    if (cb >= C || rb >= R) return;
    __shared__ float t[32][33];
    const int tx = threadIdx.x & 31, ty = threadIdx.x >> 5;
    #pragma unroll
    for (int i = ty; i < 32; i += 8)
        t[i][tx] = f2tf32f(src[(size_t)(rb + i) * C + cb + tx]);
    __syncthreads();
    #pragma unroll
    for (int i = ty; i < 32; i += 8)
        dst[(size_t)(cb + i) * R + rb + tx] = t[tx][i];
}

// 1) QKV. z<2 -> g_q/g_k row-major; z==2 -> V stored transposed into g_vt via smem.
__global__ __launch_bounds__(128) void qkv_gemm(const float* __restrict__ bq,
                                                const float* __restrict__ bk,
                                                const float* __restrict__ bv)
{
    __shared__ __align__(1024) unsigned char sbuf[SMEM_BYTES];
    const uint32_t sb = smem_u32(sbuf);
    const int z = blockIdx.z, col0 = blockIdx.x * 128, row0 = blockIdx.y * 128;
    const float* A = g_xr + (size_t)row0 * EDIM;
    const float* B = g_wt + (size_t)z * 524288 + (size_t)col0 * EDIM;
    float acc[4][8][4] = {};
    gemm_mma(A, EDIM, B, EDIM, EDIM, acc, sb);

    if (z < 2) {
        float* C = (z == 0 ? g_q : g_k) + (size_t)row0 * EH + col0;
        const float* bias = (z == 0 ? bq : bk) + col0;
        epi_plain<1>(acc, C, EH, bias);
        return;
    }
    // z==2: transpose-in-smem then coalesced store to g_vt[bh*256+hn][j]
    const int wid = threadIdx.x >> 5, lane = threadIdx.x & 31;
    const int wm = wid & 1, wn = wid >> 1;
    const int b = row0 >> 10, i0 = row0 & 1023;
    const int vrow0 = (b * 8 + (col0 >> 8)) * 256 + (col0 & 255);
    const float* bias = bv + col0;
    float* st = (float*)sbuf;                 // [64][132]
    #pragma unroll
    for (int hf = 0; hf < 2; ++hf) {
        __syncthreads();
        if (wn == hf) {
            #pragma unroll
            for (int mt = 0; mt < 4; ++mt) {
                const int m = wm * 64 + mt * 16 + (lane >> 2);
                #pragma unroll
                for (int nt = 0; nt < 8; ++nt) {
                    const int nl = nt * 8 + (lane & 3) * 2;
                    const float b0 = bias[hf * 64 + nl], b1 = bias[hf * 64 + nl + 1];
                    st[nl * 132 + m]             = f2tf32f(acc[mt][nt][0] + b0);
                    st[(nl + 1) * 132 + m]       = f2tf32f(acc[mt][nt][1] + b1);
                    st[nl * 132 + m + 8]         = f2tf32f(acc[mt][nt][2] + b0);
                    st[(nl + 1) * 132 + m + 8]   = f2tf32f(acc[mt][nt][3] + b1);
                }
            }
        }
        __syncthreads();
        #pragma unroll
        for (int r = 0; r < 16; ++r) {
            const int nl = wid * 16 + r;
            float4 v = *(float4*)(st + nl * 132 + lane * 4);
            *(float4*)(g_vt + (size_t)(vrow0 + hf * 64 + nl) * TSEQ + i0 + lane * 4) = v;
        }
    }
}

// 2) scores: store exp(Q.K/16) (tf32-rounded), zeros in masked region of diagonal tiles
__global__ __launch_bounds__(128) void scores_gemm()
{
    const int jt = blockIdx.x, it = blockIdx.y, bh = blockIdx.z;
    if (jt > it) return;
    __shared__ __align__(1024) unsigned char sbuf[SMEM_BYTES];
    const uint32_t sb = smem_u32(sbuf);
    const int b = bh >> 3, h = bh & 7;
    const float* A = g_q + (size_t)(b * TSEQ + it * 128) * EH + h * EDIM;
    const float* B = g_k + (size_t)(b * TSEQ + jt * 128) * EH + h * EDIM;
    float acc[4][8][4] = {};
    gemm_mma(A, EH, B, EH, EDIM, acc, sb);

    float* C = g_s + ((size_t)bh << 20) + (size_t)(it * 128) * TSEQ + jt * 128;
    const int wid = threadIdx.x >> 5, lane = threadIdx.x & 31;
    const int wm = wid & 1, wn = wid >> 1;
    const bool full = (jt < it);
    #pragma unroll
    for (int mt = 0; mt < 4; ++mt) {
        const int m = wm * 64 + mt * 16 + (lane >> 2);
        #pragma unroll
        for (int nt = 0; nt < 8; ++nt) {
            const int n = wn * 64 + nt * 8 + (lane & 3) * 2;
            float e0 = f2tf32f(__expf(acc[mt][nt][0] * 0.0625f));
            float e1 = f2tf32f(__expf(acc[mt][nt][1] * 0.0625f));
            float e2 = f2tf32f(__expf(acc[mt][nt][2] * 0.0625f));
            float e3 = f2tf32f(__expf(acc[mt][nt][3] * 0.0625f));
            if (!full) {                       // diagonal: local mask n<m (gi0==gj0)
                if (n >= m)         e0 = 0.f;
                if (n + 1 >= m)     e1 = 0.f;
                if (n >= m + 8)     e2 = 0.f;
                if (n + 1 >= m + 8) e3 = 0.f;
            }
            *(float2*)(C + (size_t)m * TSEQ + n)       = make_float2(e0, e1);
            *(float2*)(C + (size_t)(m + 8) * TSEQ + n) = make_float2(e2, e3);
        }
    }
}

// 3) rowsum: g_rsum[r] = sum of g_s row r over [0, klim). One warp per row.
__global__ __launch_bounds__(256) void rowsum_kernel()
{
    const int wid = threadIdx.x >> 5, lane = threadIdx.x & 31;
    const int r = blockIdx.x * 8 + wid;
    const int i = r & (TSEQ - 1);
    const int klim = ((i >> 7) + 1) << 7;
    const float* p = g_s + (size_t)r * TSEQ;
    float s = 0.f;
    for (int jb = lane * 4; jb < klim; jb += 128) {
        float4 v = *(const float4*)(p + jb);
        s += (v.x + v.y) + (v.z + v.w);
    }
    #pragma unroll
    for (int d = 16; d > 0; d >>= 1) s += __shfl_xor_sync(0xffffffffu, s, d);
    if (lane == 0) g_rsum[r] = s;
}

// 4) attnv: O = (P_unnorm @ Vt^T) * inv_rowsum, K clipped, tf32-rounded for proj
__global__ __launch_bounds__(128) void attnv_gemm()
{
    const int nt0 = blockIdx.x, it = blockIdx.y, bh = blockIdx.z;
    __shared__ __align__(1024) unsigned char sbuf[SMEM_BYTES];
    const uint32_t sb = smem_u32(sbuf);
    const int b = bh >> 3, h = bh & 7;
    const float* A = g_s + ((size_t)bh << 20) + (size_t)(it * 128) * TSEQ;
    const float* B = g_vt + ((size_t)bh * EDIM + nt0 * 128) * TSEQ;
    float acc[4][8][4] = {};
    gemm_mma(A, TSEQ, B, TSEQ, (it + 1) * 128, acc, sb);

    float* C = g_o + (size_t)(b * TSEQ + it * 128) * EH + h * EDIM + nt0 * 128;
    const float* rs = g_rsum + bh * TSEQ + it * 128;
    const int wid = threadIdx.x >> 5, lane = threadIdx.x & 31;
    const int wm = wid & 1, wn = wid >> 1;
    #pragma unroll
    for (int mt = 0; mt < 4; ++mt) {
        const int m = wm * 64 + mt * 16 + (lane >> 2);
        const float s0 = rs[m], s1 = rs[m + 8];
        const float i0 = (s0 > 0.f) ? __fdividef(1.f, s0) : 0.f;
        const float i1 = (s1 > 0.f) ? __fdividef(1.f, s1) : 0.f;
        #pragma unroll
        for (int nt = 0; nt < 8; ++nt) {
            const int n = wn * 64 + nt * 8 + (lane & 3) * 2;
            float v0 = f2tf32f(acc[mt][nt][0] * i0), v1 = f2tf32f(acc[mt][nt][1] * i0);
            float v2 = f2tf32f(acc[mt][nt][2] * i1), v3 = f2tf32f(acc[mt][nt][3] * i1);
            *(float2*)(C + (size_t)m * EH + n)       = make_float2(v0, v1);
            *(float2*)(C + (size_t)(m + 8) * EH + n) = make_float2(v2, v3);
        }
    }
}

// 5) proj
__global__ __launch_bounds__(128) void proj_gemm(const float* __restrict__ bu,
                                                 float* __restrict__ out)
{
    const int col0 = blockIdx.x * 128, row0 = blockIdx.y * 128;
    __shared__ __align__(1024) unsigned char sbuf[SMEM_BYTES];
    const uint32_t sb = smem_u32(sbuf);
    const float* A = g_o + (size_t)row0 * EH;
    const float* B = g_wt + 3 * 524288 + (size_t)col0 * EH;
    float acc[4][8][4] = {};
    gemm_mma(A, EH, B, EH, EH, acc, sb);
    epi_plain<0>(acc, out + (size_t)row0 * EDIM + col0, EDIM, bu + col0);
}

// ---------------------------------------------------------------------------
extern "C" void kernel_launch(void* const* d_in, const int* in_sizes, int n_in,
                              void* d_out, int out_size)
{
    (void)in_sizes; (void)n_in; (void)out_size;
    const float* x  = (const float*)d_in[0];
    const float* Wq = (const float*)d_in[1];
    const float* bq = (const float*)d_in[2];
    const float* Wk = (const float*)d_in[3];
    const float* bk = (const float*)d_in[4];
    const float* Wv = (const float*)d_in[5];
    const float* bv = (const float*)d_in[6];
    const float* Wu = (const float*)d_in[7];
    const float* bu = (const float*)d_in[8];
    float* out = (float*)d_out;

    round_x       <<<dim3(ROWS * EDIM / 1024), 256>>>(x);
    transpose_w   <<<dim3(64, 64, 4), 256>>>(Wq, Wk, Wv, Wu);
    qkv_gemm      <<<dim3(16, 64, 3), 128>>>(bq, bk, bv);
    scores_gemm   <<<dim3(8, 8, 64), 128>>>();
    rowsum_kernel <<<dim3(64 * TSEQ / 8), 256>>>();
    attnv_gemm    <<<dim3(2, 8, 64), 128>>>();
    proj_gemm     <<<dim3(2, 64, 1), 128>>>(bu, out);
}

// round 7
// speedup vs baseline: 6.7043x; 1.0678x over previous
#include <cuda_runtime.h>
#include <cstdint>

#define TSEQ 1024
#define EDIM 256
#define EH   2048
#define ROWS 8192

// ---------------- scratch ----------------
__device__ __align__(16) float g_xr[ROWS * (size_t)EDIM];        // tf32-rounded x
__device__ __align__(16) float g_q [ROWS * (size_t)EH];
__device__ __align__(16) float g_k [ROWS * (size_t)EH];
__device__ __align__(16) float g_vt[64 * (size_t)EDIM * TSEQ];   // [bh][n][j] (tf32-rounded)
__device__ __align__(16) float g_s [64LL * TSEQ * TSEQ];         // [bh][i][j] = exp(s/16) unnormalized
__device__ __align__(16) float g_rsum[64 * TSEQ];                // row sums of g_s
__device__ __align__(16) float g_o [ROWS * (size_t)EH];
__device__ __align__(16) float g_wt[4 * (size_t)EH * EDIM];      // WqT,WkT,WvT,WuT (K-contig)

// ---------------- helpers ----------------
__device__ __forceinline__ float f2tf32f(float f) {
    uint32_t u; asm("cvt.rna.tf32.f32 %0, %1;" : "=r"(u) : "f"(f));
    return __uint_as_float(u);
}
__device__ __forceinline__ uint32_t smem_u32(const void* p) {
    uint32_t a;
    asm("{ .reg .u64 t; cvta.to.shared.u64 t, %1; cvt.u32.u64 %0, t; }" : "=r"(a) : "l"(p));
    return a;
}
__device__ __forceinline__ void mma_tf32(float* c, const uint32_t* a, const uint32_t* b) {
    asm volatile("mma.sync.aligned.m16n8k8.row.col.f32.tf32.tf32.f32 "
                 "{%0,%1,%2,%3}, {%4,%5,%6,%7}, {%8,%9}, {%0,%1,%2,%3};"
                 : "+f"(c[0]), "+f"(c[1]), "+f"(c[2]), "+f"(c[3])
                 : "r"(a[0]), "r"(a[1]), "r"(a[2]), "r"(a[3]), "r"(b[0]), "r"(b[1]));
}
#define LDSM_X4(r0, r1, r2, r3, addr) \
    asm volatile("ldmatrix.sync.aligned.m8n8.x4.shared.b16 {%0,%1,%2,%3}, [%4];" \
                 : "=r"(r0), "=r"(r1), "=r"(r2), "=r"(r3) : "r"(addr))
#define CP16(dst, src) \
    asm volatile("cp.async.cg.shared.global [%0], [%1], 16;" :: "r"(dst), "l"(src))
#define CP_COMMIT()  asm volatile("cp.async.commit_group;")
#define CP_WAIT1()   asm volatile("cp.async.wait_group 1;")
#define CP_WAIT0()   asm volatile("cp.async.wait_group 0;")

// BK=32 stage: 128 rows x 128 B, 8x16B chunks per row, 8-way XOR swizzle
// (fill waves and all ldmatrix 8-row reads are bank-conflict-free).
#define STAGES    3
#define STAGE_B   32768            // A 16 KB + B 16 KB
#define SMEM_BYTES (STAGES * STAGE_B)

// one k-stage (BK=32) of A and B via cp.async (128 threads, 8+8 CP16/thread)
__device__ __forceinline__ void issue_stage(uint32_t sb, int s,
                                            const float* __restrict__ A, int lda,
                                            const float* __restrict__ B, int ldb,
                                            int k0, int tid)
{
    const uint32_t abase = sb + s * STAGE_B;
    const uint32_t bbase = abase + 16384;
    const int r0 = tid >> 3;             // 0..15
    const int c  = tid & 7;              // logical chunk
    const float* asrc = A + (size_t)r0 * lda + k0 + c * 4;
    const float* bsrc = B + (size_t)r0 * ldb + k0 + c * 4;
    #pragma unroll
    for (int w = 0; w < 8; ++w) {
        const int row = w * 16 + r0;
        const uint32_t off = (uint32_t)(row * 128 + ((c ^ (row & 7)) << 4));
        CP16(abase + off, asrc + (size_t)w * 16 * lda);
        CP16(bbase + off, bsrc + (size_t)w * 16 * ldb);
    }
    CP_COMMIT();
}

// compute one BK=32 stage: warp tile 64x64, frags via ldmatrix.x4
__device__ __forceinline__ void compute_stage(uint32_t sb, int s, float acc[4][8][4],
                                              int wm, int wn, int lane)
{
    const uint32_t abase = sb + s * STAGE_B;
    const uint32_t bbase = abase + 16384;
    const int arow = wm * 64 + (lane & 15);
    const int ahi  = (lane >> 4) & 1;
    const int brow0 = wn * 64 + (lane & 7);
    const int bci  = lane >> 3;          // 0..3

    #pragma unroll
    for (int kp = 0; kp < 2; ++kp) {     // k-pair: chunks kp*4..kp*4+3 (k = kp*16..+15)
        uint32_t bf[8][4];
        #pragma unroll
        for (int nt = 0; nt < 8; ++nt) {
            const int r = brow0 + nt * 8;
            const uint32_t ad = bbase + (uint32_t)(r * 128 + (((kp * 4 + bci) ^ (r & 7)) << 4));
            LDSM_X4(bf[nt][0], bf[nt][1], bf[nt][2], bf[nt][3], ad);
        }
        #pragma unroll
        for (int ks = 0; ks < 2; ++ks) {
            const int ksg = kp * 2 + ks;
            uint32_t af[4][4];
            #pragma unroll
            for (int mt = 0; mt < 4; ++mt) {
                const int r = arow + mt * 16;
                const uint32_t ad = abase + (uint32_t)(r * 128 + (((ksg * 2 + ahi) ^ (r & 7)) << 4));
                LDSM_X4(af[mt][0], af[mt][1], af[mt][2], af[mt][3], ad);
            }
            #pragma unroll
            for (int mt = 0; mt < 4; ++mt)
                #pragma unroll
                for (int nt = 0; nt < 8; ++nt)
                    mma_tf32(acc[mt][nt], af[mt], &bf[nt][ks * 2]);
        }
    }
}

// D[128x128] = A[128xK] . B[128xK]^T  (K multiple of 32; 3-buffer, 1 sync/stage)
__device__ __forceinline__ void gemm_mma(const float* __restrict__ A, int lda,
                                         const float* __restrict__ B, int ldb,
                                         int K, float acc[4][8][4], uint32_t sb)
{
    const int tid = threadIdx.x;
    const int wid = tid >> 5, lane = tid & 31;
    const int wm = wid & 1, wn = wid >> 1;
    const int KC = K >> 5;

    issue_stage(sb, 0, A, lda, B, ldb, 0, tid);
    if (KC > 1) issue_stage(sb, 1, A, lda, B, ldb, 32, tid);

    int s = 0;
    for (int c = 0; c < KC; ++c) {
        if (c + 2 < KC) CP_WAIT1(); else CP_WAIT0();
        __syncthreads();   // data-ready for stage c AND all warps done reading stage c-1
        if (c + 2 < KC) {
            int ns = s + 2; if (ns >= STAGES) ns -= STAGES;
            issue_stage(sb, ns, A, lda, B, ldb, (c + 2) * 32, tid);
        }
        compute_stage(sb, s, acc, wm, wn, lane);
        if (++s == STAGES) s = 0;
    }
    __syncthreads();       // protect smem reuse by epilogues
}

template<int ROUND>
__device__ __forceinline__ void epi_plain(float acc[4][8][4], float* C, int ldc,
                                          const float* bias)
{
    const int wid = threadIdx.x >> 5, lane = threadIdx.x & 31;
    const int wm = wid & 1, wn = wid >> 1;
    #pragma unroll
    for (int mt = 0; mt < 4; ++mt) {
        const int m = wm * 64 + mt * 16 + (lane >> 2);
        #pragma unroll
        for (int nt = 0; nt < 8; ++nt) {
            const int n = wn * 64 + nt * 8 + (lane & 3) * 2;
            float b0 = 0.f, b1 = 0.f;
            if (bias) { b0 = bias[n]; b1 = bias[n + 1]; }
            float v0 = acc[mt][nt][0] + b0, v1 = acc[mt][nt][1] + b1;
            float v2 = acc[mt][nt][2] + b0, v3 = acc[mt][nt][3] + b1;
            if (ROUND) { v0 = f2tf32f(v0); v1 = f2tf32f(v1); v2 = f2tf32f(v2); v3 = f2tf32f(v3); }
            *(float2*)(C + (size_t)m * ldc + n)       = make_float2(v0, v1);
            *(float2*)(C + (size_t)(m + 8) * ldc + n) = make_float2(v2, v3);
        }
    }
}

// ---------------- kernels ----------------

__global__ __launch_bounds__(256) void round_x(const float* __restrict__ x)
{
    const size_t i = ((size_t)blockIdx.x * 256 + threadIdx.x) * 4;
    float4 v = *(const float4*)(x + i);
    v.x = f2tf32f(v.x); v.y = f2tf32f(v.y); v.z = f2tf32f(v.z); v.w = f2tf32f(v.w);
    *(float4*)(g_xr + i) = v;
}

__global__ __launch_bounds__(256) void transpose_w(const float* __restrict__ Wq,
                                                   const float* __restrict__ Wk,
                                                   const float* __restrict__ Wv,
                                                   const float* __restrict__ Wu)
{
    const int z = blockIdx.z;
    const float* src; float* dst; int R, C;
    if (z < 3) { src = (z == 0) ? Wq : (z == 1) ? Wk : Wv; dst = g_wt + (size_t)z * 524288; R = EDIM; C = EH; }
    else       { src = Wu; dst = g_wt + 3 * 524288; R = EH; C = EDIM; }
    const int cb = blockIdx.x * 32, rb = blockIdx.y * 32;
    if (cb >= C || rb >= R) return;
    __shared__ float t[32][33];
    const int tx = threadIdx.x & 31, ty = threadIdx.x >> 5;
    #pragma unroll
    for (int i = ty; i < 32; i += 8)
        t[i][tx] = f2tf32f(src[(size_t)(rb + i) * C + cb + tx]);
    __syncthreads();
    #pragma unroll
    for (int i = ty; i < 32; i += 8)
        dst[(size_t)(cb + i) * R + rb + tx] = t[tx][i];
}

// 1) QKV. z<2 -> g_q/g_k row-major; z==2 -> V stored transposed into g_vt via smem.
__global__ __launch_bounds__(128) void qkv_gemm(const float* __restrict__ bq,
                                                const float* __restrict__ bk,
                                                const float* __restrict__ bv)
{
    extern __shared__ __align__(1024) unsigned char sbuf[];
    const uint32_t sb = smem_u32(sbuf);
    const int z = blockIdx.z, col0 = blockIdx.x * 128, row0 = blockIdx.y * 128;
    const float* A = g_xr + (size_t)row0 * EDIM;
    const float* B = g_wt + (size_t)z * 524288 + (size_t)col0 * EDIM;
    float acc[4][8][4] = {};
    gemm_mma(A, EDIM, B, EDIM, EDIM, acc, sb);

    if (z < 2) {
        float* C = (z == 0 ? g_q : g_k) + (size_t)row0 * EH + col0;
        const float* bias = (z == 0 ? bq : bk) + col0;
        epi_plain<1>(acc, C, EH, bias);
        return;
    }
    const int wid = threadIdx.x >> 5, lane = threadIdx.x & 31;
    const int wm = wid & 1, wn = wid >> 1;
    const int b = row0 >> 10, i0 = row0 & 1023;
    const int vrow0 = (b * 8 + (col0 >> 8)) * 256 + (col0 & 255);
    const float* bias = bv + col0;
    float* st = (float*)sbuf;                 // [64][132]
    #pragma unroll
    for (int hf = 0; hf < 2; ++hf) {
        __syncthreads();
        if (wn == hf) {
            #pragma unroll
            for (int mt = 0; mt < 4; ++mt) {
                const int m = wm * 64 + mt * 16 + (lane >> 2);
                #pragma unroll
                for (int nt = 0; nt < 8; ++nt) {
                    const int nl = nt * 8 + (lane & 3) * 2;
                    const float b0 = bias[hf * 64 + nl], b1 = bias[hf * 64 + nl + 1];
                    st[nl * 132 + m]             = f2tf32f(acc[mt][nt][0] + b0);
                    st[(nl + 1) * 132 + m]       = f2tf32f(acc[mt][nt][1] + b1);
                    st[nl * 132 + m + 8]         = f2tf32f(acc[mt][nt][2] + b0);
                    st[(nl + 1) * 132 + m + 8]   = f2tf32f(acc[mt][nt][3] + b1);
                }
            }
        }
        __syncthreads();
        #pragma unroll
        for (int r = 0; r < 16; ++r) {
            const int nl = wid * 16 + r;
            float4 v = *(float4*)(st + nl * 132 + lane * 4);
            *(float4*)(g_vt + (size_t)(vrow0 + hf * 64 + nl) * TSEQ + i0 + lane * 4) = v;
        }
    }
}

// 2) scores: store exp(Q.K/16) (tf32-rounded), zeros in masked region of diagonal tiles
__global__ __launch_bounds__(128) void scores_gemm()
{
    const int jt = blockIdx.x, it = blockIdx.y, bh = blockIdx.z;
    if (jt > it) return;
    extern __shared__ __align__(1024) unsigned char sbuf[];
    const uint32_t sb = smem_u32(sbuf);
    const int b = bh >> 3, h = bh & 7;
    const float* A = g_q + (size_t)(b * TSEQ + it * 128) * EH + h * EDIM;
    const float* B = g_k + (size_t)(b * TSEQ + jt * 128) * EH + h * EDIM;
    float acc[4][8][4] = {};
    gemm_mma(A, EH, B, EH, EDIM, acc, sb);

    float* C = g_s + ((size_t)bh << 20) + (size_t)(it * 128) * TSEQ + jt * 128;
    const int wid = threadIdx.x >> 5, lane = threadIdx.x & 31;
    const int wm = wid & 1, wn = wid >> 1;
    const bool full = (jt < it);
    #pragma unroll
    for (int mt = 0; mt < 4; ++mt) {
        const int m = wm * 64 + mt * 16 + (lane >> 2);
        #pragma unroll
        for (int nt = 0; nt < 8; ++nt) {
            const int n = wn * 64 + nt * 8 + (lane & 3) * 2;
            float e0 = f2tf32f(__expf(acc[mt][nt][0] * 0.0625f));
            float e1 = f2tf32f(__expf(acc[mt][nt][1] * 0.0625f));
            float e2 = f2tf32f(__expf(acc[mt][nt][2] * 0.0625f));
            float e3 = f2tf32f(__expf(acc[mt][nt][3] * 0.0625f));
            if (!full) {
                if (n >= m)         e0 = 0.f;
                if (n + 1 >= m)     e1 = 0.f;
                if (n >= m + 8)     e2 = 0.f;
                if (n + 1 >= m + 8) e3 = 0.f;
            }
            *(float2*)(C + (size_t)m * TSEQ + n)       = make_float2(e0, e1);
            *(float2*)(C + (size_t)(m + 8) * TSEQ + n) = make_float2(e2, e3);
        }
    }
}

// 3) rowsum
__global__ __launch_bounds__(256) void rowsum_kernel()
{
    const int wid = threadIdx.x >> 5, lane = threadIdx.x & 31;
    const int r = blockIdx.x * 8 + wid;
    const int i = r & (TSEQ - 1);
    const int klim = ((i >> 7) + 1) << 7;
    const float* p = g_s + (size_t)r * TSEQ;
    float s = 0.f;
    for (int jb = lane * 4; jb < klim; jb += 128) {
        float4 v = *(const float4*)(p + jb);
        s += (v.x + v.y) + (v.z + v.w);
    }
    #pragma unroll
    for (int d = 16; d > 0; d >>= 1) s += __shfl_xor_sync(0xffffffffu, s, d);
    if (lane == 0) g_rsum[r] = s;
}

// 4) attnv: O = (P_unnorm @ Vt^T) * inv_rowsum, K clipped, tf32-rounded for proj
__global__ __launch_bounds__(128) void attnv_gemm()
{
    const int nt0 = blockIdx.x, it = blockIdx.y, bh = blockIdx.z;
    extern __shared__ __align__(1024) unsigned char sbuf[];
    const uint32_t sb = smem_u32(sbuf);
    const int b = bh >> 3, h = bh & 7;
    const float* A = g_s + ((size_t)bh << 20) + (size_t)(it * 128) * TSEQ;
    const float* B = g_vt + ((size_t)bh * EDIM + nt0 * 128) * TSEQ;
    float acc[4][8][4] = {};
    gemm_mma(A, TSEQ, B, TSEQ, (it + 1) * 128, acc, sb);

    float* C = g_o + (size_t)(b * TSEQ + it * 128) * EH + h * EDIM + nt0 * 128;
    const float* rs = g_rsum + bh * TSEQ + it * 128;
    const int wid = threadIdx.x >> 5, lane = threadIdx.x & 31;
    const int wm = wid & 1, wn = wid >> 1;
    #pragma unroll
    for (int mt = 0; mt < 4; ++mt) {
        const int m = wm * 64 + mt * 16 + (lane >> 2);
        const float s0 = rs[m], s1 = rs[m + 8];
        const float i0 = (s0 > 0.f) ? __fdividef(1.f, s0) : 0.f;
        const float i1 = (s1 > 0.f) ? __fdividef(1.f, s1) : 0.f;
        #pragma unroll
        for (int nt = 0; nt < 8; ++nt) {
            const int n = wn * 64 + nt * 8 + (lane & 3) * 2;
            float v0 = f2tf32f(acc[mt][nt][0] * i0), v1 = f2tf32f(acc[mt][nt][1] * i0);
            float v2 = f2tf32f(acc[mt][nt][2] * i1), v3 = f2tf32f(acc[mt][nt][3] * i1);
            *(float2*)(C + (size_t)m * EH + n)       = make_float2(v0, v1);
            *(float2*)(C + (size_t)(m + 8) * EH + n) = make_float2(v2, v3);
        }
    }
}

// 5) proj
__global__ __launch_bounds__(128) void proj_gemm(const float* __restrict__ bu,
                                                 float* __restrict__ out)
{
    const int col0 = blockIdx.x * 128, row0 = blockIdx.y * 128;
    extern __shared__ __align__(1024) unsigned char sbuf[];
    const uint32_t sb = smem_u32(sbuf);
    const float* A = g_o + (size_t)row0 * EH;
    const float* B = g_wt + 3 * 524288 + (size_t)col0 * EH;
    float acc[4][8][4] = {};
    gemm_mma(A, EH, B, EH, EH, acc, sb);
    epi_plain<0>(acc, out + (size_t)row0 * EDIM + col0, EDIM, bu + col0);
}

// ---------------------------------------------------------------------------
extern "C" void kernel_launch(void* const* d_in, const int* in_sizes, int n_in,
                              void* d_out, int out_size)
{
    (void)in_sizes; (void)n_in; (void)out_size;
    const float* x  = (const float*)d_in[0];
    const float* Wq = (const float*)d_in[1];
    const float* bq = (const float*)d_in[2];
    const float* Wk = (const float*)d_in[3];
    const float* bk = (const float*)d_in[4];
    const float* Wv = (const float*)d_in[5];
    const float* bv = (const float*)d_in[6];
    const float* Wu = (const float*)d_in[7];
    const float* bu = (const float*)d_in[8];
    float* out = (float*)d_out;

    static bool attr_done = false;
    if (!attr_done) {
        cudaFuncSetAttribute(qkv_gemm,   cudaFuncAttributeMaxDynamicSharedMemorySize, SMEM_BYTES);
        cudaFuncSetAttribute(scores_gemm,cudaFuncAttributeMaxDynamicSharedMemorySize, SMEM_BYTES);
        cudaFuncSetAttribute(attnv_gemm, cudaFuncAttributeMaxDynamicSharedMemorySize, SMEM_BYTES);
        cudaFuncSetAttribute(proj_gemm,  cudaFuncAttributeMaxDynamicSharedMemorySize, SMEM_BYTES);
        attr_done = true;
    }

    round_x       <<<dim3(ROWS * EDIM / 1024), 256>>>(x);
    transpose_w   <<<dim3(64, 64, 4), 256>>>(Wq, Wk, Wv, Wu);
    qkv_gemm      <<<dim3(16, 64, 3), 128, SMEM_BYTES>>>(bq, bk, bv);
    scores_gemm   <<<dim3(8, 8, 64), 128, SMEM_BYTES>>>();
    rowsum_kernel <<<dim3(64 * TSEQ / 8), 256>>>();
    attnv_gemm    <<<dim3(2, 8, 64), 128, SMEM_BYTES>>>();
    proj_gemm     <<<dim3(2, 64, 1), 128, SMEM_BYTES>>>(bu, out);
}